// round 14
// baseline (speedup 1.0000x reference)
#include <cuda_runtime.h>
#include <cuda_bf16.h>

// RangeLoss: mean((preds - adjusted_target)^2), N=8M rows, F=4 -> one float4/row.
// Single-kernel HBM-streaming reduction. Deterministic via int64 fixed-point atomics.
// FINAL (== R7/R13, best evidence: 22 regs, lowest alu%, 41.7us kernel best):
// unroll-1 indexed loop, 256 thr x 1184 CTAs, occ-8 single wave. Pinned at the
// ~6.2 TB/s path-independent LTS/DRAM streaming ceiling of sm_103a; all measured
// deltas across 13 rounds of structural variants are within run-to-run noise.

__device__ unsigned long long g_acc   = 0ULL;
__device__ unsigned int       g_count = 0u;

#define FXP_SCALE 268435456.0  // 2^28

__device__ __forceinline__ float row_loss(float4 p, float4 t) {
    // Step A, column 0
    if (fabsf(p.x) < 0.01f && t.x == 0.0f) t.x = p.x;
    if (p.x > 0.99f && p.x < 1.01f && t.x == 1.0f) t.x = p.x;
    // Step A, column 1
    if (fabsf(p.y) < 0.01f && t.y == 0.0f) t.y = p.y;
    if (p.y > 0.99f && p.y < 1.01f && t.y == 1.0f) t.y = p.y;
    // Step B, column 1 (uses post-step-A t.y)
    bool cond = (p.z > 0.9f) || ((p.y * 1.05f > t.y) && (p.y * 0.95f < t.y));
    if (cond) t.y = p.y;

    float d0 = p.x - t.x;
    float d1 = p.y - t.y;
    float d2 = p.z - t.z;
    float d3 = p.w - t.w;
    return d0 * d0 + d1 * d1 + d2 * d2 + d3 * d3;
}

__global__ void __launch_bounds__(256, 8)
rangeloss_kernel(const float4* __restrict__ preds,
                 const float4* __restrict__ target,
                 int n_rows,
                 float* __restrict__ out,
                 unsigned int n_blocks,
                 double inv_count) {
    const int stride = gridDim.x * blockDim.x;
    int idx = blockIdx.x * blockDim.x + threadIdx.x;

    float facc = 0.0f;

    // Unroll-1: exactly 2 in-flight LDG.128 per warp-iteration.
    // SM-wide queue load = 64 warps * 2 = 128 < ~248 L1tex wavefront entries,
    // avoiding cross-CTA queue-contention spread while saturating DRAM.
    for (; idx < n_rows; idx += stride) {
        float4 p = __ldcs(&preds[idx]);
        float4 t = __ldcs(&target[idx]);
        facc += row_loss(p, t);
    }

    // Warp reduce in float (per-lane sums are small; fp32 ample for 1e-3 tol)
    #pragma unroll
    for (int off = 16; off > 0; off >>= 1)
        facc += __shfl_down_sync(0xFFFFFFFFu, facc, off);

    __shared__ float swarp[8];  // 256 threads = 8 warps
    int lane = threadIdx.x & 31;
    int wid  = threadIdx.x >> 5;
    if (lane == 0) swarp[wid] = facc;
    __syncthreads();

    if (threadIdx.x == 0) {
        double bsum = 0.0;
        #pragma unroll
        for (int w = 0; w < 8; w++) bsum += (double)swarp[w];

        // Deterministic device-wide accumulation: fixed-point int64
        unsigned long long fx = (unsigned long long)(bsum * FXP_SCALE + 0.5);
        atomicAdd(&g_acc, fx);
        __threadfence();
        unsigned int done = atomicAdd(&g_count, 1u);
        if (done == n_blocks - 1u) {
            unsigned long long total_fx = atomicAdd(&g_acc, 0ULL);
            double total = (double)total_fx / FXP_SCALE;
            out[0] = (float)(total * inv_count);
            // Reset for next graph replay
            atomicExch(&g_acc, 0ULL);
            atomicExch(&g_count, 0u);
        }
    }
}

extern "C" void kernel_launch(void* const* d_in, const int* in_sizes, int n_in,
                              void* d_out, int out_size) {
    const float4* preds  = (const float4*)d_in[0];
    const float4* target = (const float4*)d_in[1];
    float* out = (float*)d_out;

    long long n_elems = (long long)in_sizes[0];   // N * 4
    int n_rows = (int)(n_elems / 4);

    const int threads = 256;
    int blocks = 148 * 8;  // exactly one resident wave at occ=8
    if ((long long)blocks * threads > (long long)n_rows)
        blocks = (n_rows + threads - 1) / threads;
    if (blocks < 1) blocks = 1;

    rangeloss_kernel<<<blocks, threads>>>(preds, target, n_rows, out,
                                          (unsigned int)blocks,
                                          1.0 / (double)n_elems);
}

// round 15
// speedup vs baseline: 1.0537x; 1.0537x over previous
#include <cuda_runtime.h>
#include <cuda_bf16.h>

// RangeLoss: mean((preds - adjusted_target)^2), N=8M rows, F=4 -> one float4/row.
// Single-kernel HBM-streaming reduction. Deterministic via int64 fixed-point atomics.
// FINAL (== R7/R13/R14, best evidence: 22 regs, lowest alu%, 41.7us kernel best):
// unroll-1 indexed loop, 256 thr x 1184 CTAs, occ-8 single wave. Pinned at the
// ~6.2 TB/s path-independent LTS/DRAM streaming ceiling of sm_103a; all measured
// deltas across 14 rounds of structural variants are within run-to-run noise.

__device__ unsigned long long g_acc   = 0ULL;
__device__ unsigned int       g_count = 0u;

#define FXP_SCALE 268435456.0  // 2^28

__device__ __forceinline__ float row_loss(float4 p, float4 t) {
    // Step A, column 0
    if (fabsf(p.x) < 0.01f && t.x == 0.0f) t.x = p.x;
    if (p.x > 0.99f && p.x < 1.01f && t.x == 1.0f) t.x = p.x;
    // Step A, column 1
    if (fabsf(p.y) < 0.01f && t.y == 0.0f) t.y = p.y;
    if (p.y > 0.99f && p.y < 1.01f && t.y == 1.0f) t.y = p.y;
    // Step B, column 1 (uses post-step-A t.y)
    bool cond = (p.z > 0.9f) || ((p.y * 1.05f > t.y) && (p.y * 0.95f < t.y));
    if (cond) t.y = p.y;

    float d0 = p.x - t.x;
    float d1 = p.y - t.y;
    float d2 = p.z - t.z;
    float d3 = p.w - t.w;
    return d0 * d0 + d1 * d1 + d2 * d2 + d3 * d3;
}

__global__ void __launch_bounds__(256, 8)
rangeloss_kernel(const float4* __restrict__ preds,
                 const float4* __restrict__ target,
                 int n_rows,
                 float* __restrict__ out,
                 unsigned int n_blocks,
                 double inv_count) {
    const int stride = gridDim.x * blockDim.x;
    int idx = blockIdx.x * blockDim.x + threadIdx.x;

    float facc = 0.0f;

    // Unroll-1: exactly 2 in-flight LDG.128 per warp-iteration.
    // SM-wide queue load = 64 warps * 2 = 128 < ~248 L1tex wavefront entries,
    // avoiding cross-CTA queue-contention spread while saturating DRAM.
    for (; idx < n_rows; idx += stride) {
        float4 p = __ldcs(&preds[idx]);
        float4 t = __ldcs(&target[idx]);
        facc += row_loss(p, t);
    }

    // Warp reduce in float (per-lane sums are small; fp32 ample for 1e-3 tol)
    #pragma unroll
    for (int off = 16; off > 0; off >>= 1)
        facc += __shfl_down_sync(0xFFFFFFFFu, facc, off);

    __shared__ float swarp[8];  // 256 threads = 8 warps
    int lane = threadIdx.x & 31;
    int wid  = threadIdx.x >> 5;
    if (lane == 0) swarp[wid] = facc;
    __syncthreads();

    if (threadIdx.x == 0) {
        double bsum = 0.0;
        #pragma unroll
        for (int w = 0; w < 8; w++) bsum += (double)swarp[w];

        // Deterministic device-wide accumulation: fixed-point int64
        unsigned long long fx = (unsigned long long)(bsum * FXP_SCALE + 0.5);
        atomicAdd(&g_acc, fx);
        __threadfence();
        unsigned int done = atomicAdd(&g_count, 1u);
        if (done == n_blocks - 1u) {
            unsigned long long total_fx = atomicAdd(&g_acc, 0ULL);
            double total = (double)total_fx / FXP_SCALE;
            out[0] = (float)(total * inv_count);
            // Reset for next graph replay
            atomicExch(&g_acc, 0ULL);
            atomicExch(&g_count, 0u);
        }
    }
}

extern "C" void kernel_launch(void* const* d_in, const int* in_sizes, int n_in,
                              void* d_out, int out_size) {
    const float4* preds  = (const float4*)d_in[0];
    const float4* target = (const float4*)d_in[1];
    float* out = (float*)d_out;

    long long n_elems = (long long)in_sizes[0];   // N * 4
    int n_rows = (int)(n_elems / 4);

    const int threads = 256;
    int blocks = 148 * 8;  // exactly one resident wave at occ=8
    if ((long long)blocks * threads > (long long)n_rows)
        blocks = (n_rows + threads - 1) / threads;
    if (blocks < 1) blocks = 1;

    rangeloss_kernel<<<blocks, threads>>>(preds, target, n_rows, out,
                                          (unsigned int)blocks,
                                          1.0 / (double)n_elems);
}